// round 1
// baseline (speedup 1.0000x reference)
#include <cuda_runtime.h>
#include <cuda_bf16.h>
#include <math.h>

// Problem dims (fixed by the dataset)
#define S_SAMP 32
#define BATCH  1024
#define D_IN   784
#define D_H    1024
#define D_OUT  10

// ---------------------------------------------------------------------------
// Scratch (no cudaMalloc allowed): static __device__ arrays.
// ---------------------------------------------------------------------------
__device__ float g_act0[(size_t)S_SAMP * BATCH * D_H];   // 134 MB
__device__ float g_act1[(size_t)S_SAMP * BATCH * D_H];   // 134 MB
__device__ float g_sig0[(size_t)D_IN * D_H];             // exp(0.5*wv0)
__device__ float g_sig1[(size_t)D_H * D_H];              // exp(0.5*wv1)
__device__ float g_b0[S_SAMP * D_H];                     // sampled biases layer0
__device__ float g_b1[S_SAMP * D_H];                     // sampled biases layer1
__device__ float g_wl[S_SAMP * D_H * D_OUT];             // sampled last-layer W
__device__ float g_bl[S_SAMP * D_OUT];                   // sampled last-layer b

// ---------------------------------------------------------------------------
// Prep kernels
// ---------------------------------------------------------------------------
__global__ void prep_sigma(const float* __restrict__ v, float* __restrict__ sig, int n) {
    int i = blockIdx.x * blockDim.x + threadIdx.x;
    if (i < n) sig[i] = expf(0.5f * v[i]);
}

// out[s*n+i] = e[s*n+i] * exp(0.5*v[i]) + m[i]
__global__ void prep_sample(const float* __restrict__ e, const float* __restrict__ v,
                            const float* __restrict__ m, float* __restrict__ out,
                            int n, int total) {
    int i = blockIdx.x * blockDim.x + threadIdx.x;
    if (i < total) {
        int j = i % n;
        out[i] = fmaf(e[i], expf(0.5f * v[j]), m[j]);
    }
}

// ---------------------------------------------------------------------------
// Main sampled GEMM:
//   C[s] (M x N) = relu?( A[s] (M x K) @ (we[s]*sig + wm) (K x N) + bias[s] )
// Tiling: 128x128x8, 256 threads, 8x8 per-thread micro-tile.
// ---------------------------------------------------------------------------
#define BM 128
#define BN 128
#define BK 8
#define TM 8
#define TN 8

__global__ void __launch_bounds__(256, 2) gemm_sampled(
    const float* __restrict__ A, size_t aStrideS,
    const float* __restrict__ we,
    const float* __restrict__ sig,
    const float* __restrict__ wm,
    const float* __restrict__ bias,   // (S, N)
    float* __restrict__ C,            // (S, M, N)
    int M, int N, int K, int do_relu)
{
    const int s  = blockIdx.z;
    const int m0 = blockIdx.y * BM;
    const int n0 = blockIdx.x * BN;

    const float* Ab  = A  + (size_t)s * aStrideS;
    const float* web = we + (size_t)s * (size_t)K * N;

    __shared__ float As[BK][BM];   // transposed A tile
    __shared__ float Ws[BK][BN];

    const int tid = threadIdx.x;
    const int tx  = tid & 15;      // 0..15  -> n sub-tile
    const int ty  = tid >> 4;      // 0..15  -> m sub-tile

    // A-tile loader: 128 rows x 8 cols, 2 threads/row, one float4 each
    const int arow = tid >> 1;           // 0..127
    const int acol = (tid & 1) * 4;      // 0 or 4
    // W-tile loader: 8 rows x 128 cols, 32 threads/row, one float4 each
    const int wrow = tid >> 5;           // 0..7
    const int wcol = (tid & 31) * 4;     // 0..124

    float acc[TM][TN];
#pragma unroll
    for (int i = 0; i < TM; i++)
#pragma unroll
        for (int j = 0; j < TN; j++) acc[i][j] = 0.0f;

    for (int k0 = 0; k0 < K; k0 += BK) {
        // ---- load A tile (transposed into smem) ----
        float4 av = *(const float4*)(Ab + (size_t)(m0 + arow) * K + (k0 + acol));
        As[acol + 0][arow] = av.x;
        As[acol + 1][arow] = av.y;
        As[acol + 2][arow] = av.z;
        As[acol + 3][arow] = av.w;

        // ---- load + sample W tile: w = we * sigma + wm ----
        size_t woff = (size_t)(k0 + wrow) * N + (n0 + wcol);
        float4 e  = *(const float4*)(web + woff);
        float4 sg = *(const float4*)(sig + woff);
        float4 mm = *(const float4*)(wm  + woff);
        float4 w;
        w.x = fmaf(e.x, sg.x, mm.x);
        w.y = fmaf(e.y, sg.y, mm.y);
        w.z = fmaf(e.z, sg.z, mm.z);
        w.w = fmaf(e.w, sg.w, mm.w);
        *(float4*)&Ws[wrow][wcol] = w;

        __syncthreads();

#pragma unroll
        for (int kk = 0; kk < BK; kk++) {
            float a[TM], b[TN];
            *(float4*)&a[0] = *(const float4*)&As[kk][ty * TM];
            *(float4*)&a[4] = *(const float4*)&As[kk][ty * TM + 4];
            *(float4*)&b[0] = *(const float4*)&Ws[kk][tx * TN];
            *(float4*)&b[4] = *(const float4*)&Ws[kk][tx * TN + 4];
#pragma unroll
            for (int i = 0; i < TM; i++)
#pragma unroll
                for (int j = 0; j < TN; j++)
                    acc[i][j] = fmaf(a[i], b[j], acc[i][j]);
        }
        __syncthreads();
    }

    // ---- epilogue: bias + optional relu ----
    float bb[TN];
    *(float4*)&bb[0] = *(const float4*)(bias + (size_t)s * N + n0 + tx * TN);
    *(float4*)&bb[4] = *(const float4*)(bias + (size_t)s * N + n0 + tx * TN + 4);

#pragma unroll
    for (int i = 0; i < TM; i++) {
        size_t off = ((size_t)s * M + (m0 + ty * TM + i)) * N + (n0 + tx * TN);
        float v[TN];
#pragma unroll
        for (int j = 0; j < TN; j++) {
            v[j] = acc[i][j] + bb[j];
            if (do_relu) v[j] = fmaxf(v[j], 0.0f);
        }
        *(float4*)(C + off)     = *(float4*)&v[0];
        *(float4*)(C + off + 4) = *(float4*)&v[4];
    }
}

// ---------------------------------------------------------------------------
// Last layer: out[s,b,o] = act[s,b,:] . wl[s,:,o] + bl[s,o]   (N = 10)
// Block: 128 rows of one sample; 256 threads; thread -> (row, 5 outputs).
// ---------------------------------------------------------------------------
__global__ void __launch_bounds__(256) layer_out(
    const float* __restrict__ act,   // (S, B, D_H)
    const float* __restrict__ wls,   // (S, D_H, D_OUT)
    const float* __restrict__ bls,   // (S, D_OUT)
    float* __restrict__ out)         // (S, B, D_OUT)
{
    const int s  = blockIdx.y;
    const int m0 = blockIdx.x * 128;

    __shared__ float As[128][33];    // padded: 33 stride -> conflict-free
    __shared__ float ws[32 * D_OUT]; // 320 floats per k-chunk

    const int tid   = threadIdx.x;
    const int crow  = tid >> 1;          // 0..127
    const int obase = (tid & 1) * 5;     // 0 or 5

    float acc[5] = {0.f, 0.f, 0.f, 0.f, 0.f};

    const int lr = tid >> 3;             // 0..31 base row
    const int lk = (tid & 7) * 4;        // 0..28

    for (int kt = 0; kt < D_H; kt += 32) {
        // load act chunk: 128 rows x 32 k, coalesced float4
#pragma unroll
        for (int rr = 0; rr < 4; rr++) {
            int r = lr + rr * 32;
            float4 v = *(const float4*)(act + ((size_t)s * BATCH + m0 + r) * D_H + kt + lk);
            As[r][lk + 0] = v.x;
            As[r][lk + 1] = v.y;
            As[r][lk + 2] = v.z;
            As[r][lk + 3] = v.w;
        }
        // load W chunk: 32 x 10 contiguous floats
        for (int i = tid; i < 32 * D_OUT; i += 256)
            ws[i] = wls[(size_t)s * D_H * D_OUT + kt * D_OUT + i];
        __syncthreads();

#pragma unroll
        for (int k = 0; k < 32; k++) {
            float a = As[crow][k];
#pragma unroll
            for (int j = 0; j < 5; j++)
                acc[j] = fmaf(a, ws[k * D_OUT + obase + j], acc[j]);
        }
        __syncthreads();
    }

#pragma unroll
    for (int j = 0; j < 5; j++)
        out[((size_t)s * BATCH + m0 + crow) * D_OUT + obase + j] =
            acc[j] + bls[s * D_OUT + obase + j];
}

// ---------------------------------------------------------------------------
// kernel_launch
// ---------------------------------------------------------------------------
extern "C" void kernel_launch(void* const* d_in, const int* in_sizes, int n_in,
                              void* d_out, int out_size) {
    const float* x   = (const float*)d_in[0];
    const float* wm0 = (const float*)d_in[1];
    const float* wv0 = (const float*)d_in[2];
    const float* bm0 = (const float*)d_in[3];
    const float* bv0 = (const float*)d_in[4];
    const float* wm1 = (const float*)d_in[5];
    const float* wv1 = (const float*)d_in[6];
    const float* bm1 = (const float*)d_in[7];
    const float* bv1 = (const float*)d_in[8];
    const float* wlm = (const float*)d_in[9];
    const float* wlv = (const float*)d_in[10];
    const float* blm = (const float*)d_in[11];
    const float* blv = (const float*)d_in[12];
    const float* we0 = (const float*)d_in[13];
    const float* be0 = (const float*)d_in[14];
    const float* we1 = (const float*)d_in[15];
    const float* be1 = (const float*)d_in[16];
    const float* wel = (const float*)d_in[17];
    const float* bel = (const float*)d_in[18];
    float* out = (float*)d_out;

    float *act0, *act1, *sig0, *sig1, *b0, *b1, *wl, *bl;
    cudaGetSymbolAddress((void**)&act0, g_act0);
    cudaGetSymbolAddress((void**)&act1, g_act1);
    cudaGetSymbolAddress((void**)&sig0, g_sig0);
    cudaGetSymbolAddress((void**)&sig1, g_sig1);
    cudaGetSymbolAddress((void**)&b0,   g_b0);
    cudaGetSymbolAddress((void**)&b1,   g_b1);
    cudaGetSymbolAddress((void**)&wl,   g_wl);
    cudaGetSymbolAddress((void**)&bl,   g_bl);

    // ---- prep: sigmas ----
    {
        int n = D_IN * D_H;
        prep_sigma<<<(n + 255) / 256, 256>>>(wv0, sig0, n);
        n = D_H * D_H;
        prep_sigma<<<(n + 255) / 256, 256>>>(wv1, sig1, n);
    }
    // ---- prep: sampled biases + last-layer weights ----
    {
        int n = D_H, total = S_SAMP * D_H;
        prep_sample<<<(total + 255) / 256, 256>>>(be0, bv0, bm0, b0, n, total);
        prep_sample<<<(total + 255) / 256, 256>>>(be1, bv1, bm1, b1, n, total);
        n = D_H * D_OUT; total = S_SAMP * D_H * D_OUT;
        prep_sample<<<(total + 255) / 256, 256>>>(wel, wlv, wlm, wl, n, total);
        n = D_OUT; total = S_SAMP * D_OUT;
        prep_sample<<<(total + 255) / 256, 256>>>(bel, blv, blm, bl, n, total);
    }

    // ---- layer 0: act0 = relu(x @ W0_s + b0_s) ----
    {
        dim3 grid(D_H / BN, BATCH / BM, S_SAMP);
        gemm_sampled<<<grid, 256>>>(x, /*aStrideS=*/0,
                                    we0, sig0, wm0, b0, act0,
                                    BATCH, D_H, D_IN, /*relu=*/1);
    }
    // ---- layer 1: act1 = relu(act0_s @ W1_s + b1_s) ----
    {
        dim3 grid(D_H / BN, BATCH / BM, S_SAMP);
        gemm_sampled<<<grid, 256>>>(act0, (size_t)BATCH * D_H,
                                    we1, sig1, wm1, b1, act1,
                                    BATCH, D_H, D_H, /*relu=*/1);
    }
    // ---- layer 2: logits ----
    {
        dim3 grid(BATCH / 128, S_SAMP);
        layer_out<<<grid, 256>>>(act1, wl, bl, out);
    }
}

// round 3
// speedup vs baseline: 1.7580x; 1.7580x over previous
#include <cuda_runtime.h>
#include <cuda_bf16.h>
#include <cstdint>
#include <math.h>

#define S_SAMP 32
#define BATCH  1024
#define D_IN   784
#define D_H    1024
#define D_OUT  10
#define K0PAD  832            // 784 padded to multiple of 32

// ---------------------------------------------------------------------------
// Device scratch (static: no cudaMalloc allowed)
// ---------------------------------------------------------------------------
__device__ __nv_bfloat16 g_xhi[(size_t)BATCH * K0PAD];
__device__ __nv_bfloat16 g_xlo[(size_t)BATCH * K0PAD];
__device__ __nv_bfloat16 g_w0hi[(size_t)S_SAMP * D_H * K0PAD];   // [S][N][Kpad] transposed
__device__ __nv_bfloat16 g_w0lo[(size_t)S_SAMP * D_H * K0PAD];
__device__ __nv_bfloat16 g_w1hi[(size_t)S_SAMP * D_H * D_H];
__device__ __nv_bfloat16 g_w1lo[(size_t)S_SAMP * D_H * D_H];
__device__ __nv_bfloat16 g_a0hi[(size_t)S_SAMP * BATCH * D_H];
__device__ __nv_bfloat16 g_a0lo[(size_t)S_SAMP * BATCH * D_H];
__device__ float         g_act1[(size_t)S_SAMP * BATCH * D_H];
__device__ float g_b0[S_SAMP * D_H];
__device__ float g_b1[S_SAMP * D_H];
__device__ float g_wl[S_SAMP * D_H * D_OUT];
__device__ float g_bl[S_SAMP * D_OUT];

// ---------------------------------------------------------------------------
// PTX helpers (arch-neutral only: cp.async, ldmatrix, mma.sync)
// ---------------------------------------------------------------------------
__device__ __forceinline__ uint32_t smem_u32(const void* p) {
    uint32_t a;
    asm("{ .reg .u64 t; cvta.to.shared.u64 t, %1; cvt.u32.u64 %0, t; }" : "=r"(a) : "l"(p));
    return a;
}
__device__ __forceinline__ void cp16(uint32_t dst, const void* src) {
    asm volatile("cp.async.cg.shared.global [%0], [%1], 16;" :: "r"(dst), "l"(src) : "memory");
}
#define CP_COMMIT() asm volatile("cp.async.commit_group;" ::: "memory")
#define CP_WAIT(n)  asm volatile("cp.async.wait_group %0;" :: "n"(n) : "memory")

__device__ __forceinline__ void ldsm4(uint32_t* r, uint32_t addr) {
    asm volatile("ldmatrix.sync.aligned.m8n8.x4.shared.b16 {%0,%1,%2,%3}, [%4];"
        : "=r"(r[0]), "=r"(r[1]), "=r"(r[2]), "=r"(r[3]) : "r"(addr));
}
__device__ __forceinline__ void mma_bf16(float* d, const uint32_t* a, const uint32_t* b) {
    asm volatile("mma.sync.aligned.m16n8k16.row.col.f32.bf16.bf16.f32 "
        "{%0,%1,%2,%3}, {%4,%5,%6,%7}, {%8,%9}, {%0,%1,%2,%3};"
        : "+f"(d[0]), "+f"(d[1]), "+f"(d[2]), "+f"(d[3])
        : "r"(a[0]), "r"(a[1]), "r"(a[2]), "r"(a[3]), "r"(b[0]), "r"(b[1]));
}

// ---------------------------------------------------------------------------
// Prep kernels
// ---------------------------------------------------------------------------
__global__ void prep_x(const float* __restrict__ x,
                       __nv_bfloat16* __restrict__ xhi, __nv_bfloat16* __restrict__ xlo) {
    int i = blockIdx.x * blockDim.x + threadIdx.x;
    if (i >= BATCH * K0PAD) return;
    int b = i / K0PAD, k = i - b * K0PAD;
    float v = (k < D_IN) ? x[b * D_IN + k] : 0.0f;
    __nv_bfloat16 h = __float2bfloat16(v);
    xhi[i] = h;
    xlo[i] = __float2bfloat16(v - __bfloat162float(h));
}

// Sample + transpose weights: out[s][n][kpad] = we[s][k][n]*exp(.5 wv[k][n]) + wm[k][n]
__global__ void prep_wt(const float* __restrict__ we, const float* __restrict__ wv,
                        const float* __restrict__ wm,
                        __nv_bfloat16* __restrict__ whi, __nv_bfloat16* __restrict__ wlo,
                        int K, int N, int Kpad) {
    __shared__ float t[32][33];
    int s = blockIdx.z;
    int k0 = blockIdx.x * 32, n0 = blockIdx.y * 32;
    int tx = threadIdx.x, ty = threadIdx.y;       // 32 x 8
#pragma unroll
    for (int i = 0; i < 4; i++) {
        int k = k0 + ty + i * 8;
        float val = 0.0f;
        if (k < K) {
            size_t idx = (size_t)k * N + n0 + tx;
            val = fmaf(we[(size_t)s * K * N + idx], expf(0.5f * wv[idx]), wm[idx]);
        }
        t[ty + i * 8][tx] = val;
    }
    __syncthreads();
#pragma unroll
    for (int i = 0; i < 4; i++) {
        int n = n0 + ty + i * 8;
        float v = t[tx][ty + i * 8];
        __nv_bfloat16 h = __float2bfloat16(v);
        size_t off = ((size_t)s * N + n) * Kpad + k0 + tx;
        whi[off] = h;
        wlo[off] = __float2bfloat16(v - __bfloat162float(h));
    }
}

__global__ void prep_sample(const float* __restrict__ e, const float* __restrict__ v,
                            const float* __restrict__ m, float* __restrict__ out,
                            int n, int total) {
    int i = blockIdx.x * blockDim.x + threadIdx.x;
    if (i < total) {
        int j = i % n;
        out[i] = fmaf(e[i], expf(0.5f * v[j]), m[j]);
    }
}

// ---------------------------------------------------------------------------
// HMMA GEMM with fused bf16 hi/lo split (3-term):
//   C[s] = relu(A[s] @ W[s]^T + bias[s])
//   A: [.][M][Kpad] bf16 hi/lo, W: [S][N][Kpad] bf16 hi/lo (K-major rows).
//   CTA tile 128x128x32, 8 warps (warp tile 32x64), double-buffered cp.async.
//   Smem rows padded to 80B (5*16B, coprime 8 -> LDSM conflict-free, no XOR).
//   mode 0: write bf16 hi/lo (feeds next GEMM); mode 1: write fp32.
// ---------------------------------------------------------------------------
#define GBM 128
#define GBN 128
#define GBK 32
#define ROWB 80                      // padded smem row stride (bytes)
#define MATB (128 * ROWB)            // 10240 B per matrix tile
#define STAGEB (4 * MATB)            // Ahi,Alo,Bhi,Blo = 40960 B
#define SMEM_TOTAL (2 * STAGEB)      // 81920 B

__global__ void __launch_bounds__(256, 2) gemm_mma(
    const __nv_bfloat16* __restrict__ Ahi, const __nv_bfloat16* __restrict__ Alo,
    size_t aStrideS, int Kpad,
    const __nv_bfloat16* __restrict__ Whi, const __nv_bfloat16* __restrict__ Wlo,
    const float* __restrict__ bias,
    float* __restrict__ Cf,
    __nv_bfloat16* __restrict__ Chi, __nv_bfloat16* __restrict__ Clo,
    int mode)
{
    extern __shared__ __align__(16) char dynsmem[];
    const uint32_t sbase = smem_u32(dynsmem);

    const int tid  = threadIdx.x;
    const int wid  = tid >> 5;
    const int lane = tid & 31;
    const int s  = blockIdx.z;
    const int m0 = blockIdx.y * GBM;
    const int n0 = blockIdx.x * GBN;

    const int warp_m = wid >> 1;          // 0..3 -> 32-row strip
    const int warp_n = wid & 1;           // 0..1 -> 64-col strip

    const __nv_bfloat16* aHiG = Ahi + (size_t)s * aStrideS + (size_t)m0 * Kpad;
    const __nv_bfloat16* aLoG = Alo + (size_t)s * aStrideS + (size_t)m0 * Kpad;
    const __nv_bfloat16* wHiG = Whi + ((size_t)s * D_H + n0) * Kpad;
    const __nv_bfloat16* wLoG = Wlo + ((size_t)s * D_H + n0) * Kpad;

    // loader: 256 threads -> (row 0..127, sel hi/lo), 4 x 16B chunks per row
    const int lrow = tid & 127;
    const int lsel = tid >> 7;            // 0 = hi, 1 = lo
    const __nv_bfloat16* aSrc = (lsel ? aLoG : aHiG) + (size_t)lrow * Kpad;
    const __nv_bfloat16* bSrc = (lsel ? wLoG : wHiG) + (size_t)lrow * Kpad;
    const uint32_t aDstRow = lsel * MATB + lrow * ROWB;            // in Ahi/Alo
    const uint32_t bDstRow = (2 + lsel) * MATB + lrow * ROWB;      // in Bhi/Blo

    // ldmatrix per-lane offsets
    const uint32_t aLaneOff = (uint32_t)(lane & 15) * ROWB + (uint32_t)(lane >> 4) * 16;
    const uint32_t bLaneOff = (uint32_t)((lane & 7) + ((lane & 16) >> 1)) * ROWB
                            + (uint32_t)((lane >> 3) & 1) * 16;
    const uint32_t aWarpOff = (uint32_t)(warp_m * 32) * ROWB;
    const uint32_t bWarpOff = (uint32_t)(warp_n * 64) * ROWB;

    float acc[2][8][4];
#pragma unroll
    for (int i = 0; i < 2; i++)
#pragma unroll
        for (int j = 0; j < 8; j++)
#pragma unroll
            for (int q = 0; q < 4; q++) acc[i][j][q] = 0.0f;

    const int nchunks = Kpad / GBK;

    // prologue: load chunk 0 into stage 0
    {
        const int k0 = 0;
#pragma unroll
        for (int c = 0; c < 4; c++) {
            cp16(sbase + aDstRow + c * 16, aSrc + k0 + c * 8);
            cp16(sbase + bDstRow + c * 16, bSrc + k0 + c * 8);
        }
        CP_COMMIT();
    }

    for (int it = 0; it < nchunks; it++) {
        // prefetch next chunk
        if (it + 1 < nchunks) {
            const uint32_t st = sbase + ((it + 1) & 1) * STAGEB;
            const int k0 = (it + 1) * GBK;
#pragma unroll
            for (int c = 0; c < 4; c++) {
                cp16(st + aDstRow + c * 16, aSrc + k0 + c * 8);
                cp16(st + bDstRow + c * 16, bSrc + k0 + c * 8);
            }
            CP_COMMIT();
            CP_WAIT(1);
        } else {
            CP_WAIT(0);
        }
        __syncthreads();

        const uint32_t st  = sbase + (it & 1) * STAGEB;
        const uint32_t aHiS = st + aWarpOff + aLaneOff;
        const uint32_t aLoS = st + MATB + aWarpOff + aLaneOff;
        const uint32_t bHiS = st + 2 * MATB + bWarpOff + bLaneOff;
        const uint32_t bLoS = st + 3 * MATB + bWarpOff + bLaneOff;

#pragma unroll
        for (int ks = 0; ks < 2; ks++) {
            const uint32_t ko = ks * 32;  // 16 bf16 = 32 B per k16 step
            uint32_t ah[2][4], al[2][4], bh[16], bl[16];
#pragma unroll
            for (int mi = 0; mi < 2; mi++)
                ldsm4(ah[mi], aHiS + mi * 16 * ROWB + ko);
#pragma unroll
            for (int p = 0; p < 4; p++)
                ldsm4(&bh[p * 4], bHiS + p * 16 * ROWB + ko);
            // term 1: hi * hi
#pragma unroll
            for (int mi = 0; mi < 2; mi++)
#pragma unroll
                for (int nj = 0; nj < 8; nj++)
                    mma_bf16(acc[mi][nj], ah[mi], &bh[nj * 2]);
            // term 2: hi * lo
#pragma unroll
            for (int p = 0; p < 4; p++)
                ldsm4(&bl[p * 4], bLoS + p * 16 * ROWB + ko);
#pragma unroll
            for (int mi = 0; mi < 2; mi++)
#pragma unroll
                for (int nj = 0; nj < 8; nj++)
                    mma_bf16(acc[mi][nj], ah[mi], &bl[nj * 2]);
            // term 3: lo * hi
#pragma unroll
            for (int mi = 0; mi < 2; mi++)
                ldsm4(al[mi], aLoS + mi * 16 * ROWB + ko);
#pragma unroll
            for (int mi = 0; mi < 2; mi++)
#pragma unroll
                for (int nj = 0; nj < 8; nj++)
                    mma_bf16(acc[mi][nj], al[mi], &bh[nj * 2]);
        }
        __syncthreads();
    }

    // ---- epilogue ----
    const int colBase = n0 + warp_n * 64 + (lane & 3) * 2;
    const int rowBase = m0 + warp_m * 32 + (lane >> 2);
    float bias2[8][2];
#pragma unroll
    for (int nj = 0; nj < 8; nj++) {
        const float* bp = bias + (size_t)s * D_H + colBase + nj * 8;
        bias2[nj][0] = bp[0];
        bias2[nj][1] = bp[1];
    }

#pragma unroll
    for (int mi = 0; mi < 2; mi++) {
#pragma unroll
        for (int h = 0; h < 2; h++) {
            const int row = rowBase + mi * 16 + h * 8;
            const size_t rowOff = ((size_t)s * BATCH + row) * D_H;
#pragma unroll
            for (int nj = 0; nj < 8; nj++) {
                float v0 = fmaxf(acc[mi][nj][2 * h]     + bias2[nj][0], 0.0f);
                float v1 = fmaxf(acc[mi][nj][2 * h + 1] + bias2[nj][1], 0.0f);
                const int n = colBase + nj * 8;
                if (mode == 0) {
                    __nv_bfloat16 h0 = __float2bfloat16(v0);
                    __nv_bfloat16 h1 = __float2bfloat16(v1);
                    __nv_bfloat16 l0 = __float2bfloat16(v0 - __bfloat162float(h0));
                    __nv_bfloat16 l1 = __float2bfloat16(v1 - __bfloat162float(h1));
                    *(uint32_t*)((uint16_t*)Chi + rowOff + n) =
                        (uint32_t)__bfloat16_as_ushort(h0) | ((uint32_t)__bfloat16_as_ushort(h1) << 16);
                    *(uint32_t*)((uint16_t*)Clo + rowOff + n) =
                        (uint32_t)__bfloat16_as_ushort(l0) | ((uint32_t)__bfloat16_as_ushort(l1) << 16);
                } else {
                    *(float2*)(Cf + rowOff + n) = make_float2(v0, v1);
                }
            }
        }
    }
}

// ---------------------------------------------------------------------------
// Last layer (fp32): out[s,b,o] = act[s,b,:] . wl[s,:,o] + bl[s,o]
// ---------------------------------------------------------------------------
__global__ void __launch_bounds__(256) layer_out(
    const float* __restrict__ act, const float* __restrict__ wls,
    const float* __restrict__ bls, float* __restrict__ out)
{
    const int s  = blockIdx.y;
    const int m0 = blockIdx.x * 128;

    __shared__ float As[128][33];
    __shared__ float ws[32 * D_OUT];

    const int tid   = threadIdx.x;
    const int crow  = tid >> 1;
    const int obase = (tid & 1) * 5;

    float acc[5] = {0.f, 0.f, 0.f, 0.f, 0.f};
    const int lr = tid >> 3;
    const int lk = (tid & 7) * 4;

    for (int kt = 0; kt < D_H; kt += 32) {
#pragma unroll
        for (int rr = 0; rr < 4; rr++) {
            int r = lr + rr * 32;
            float4 v = *(const float4*)(act + ((size_t)s * BATCH + m0 + r) * D_H + kt + lk);
            As[r][lk + 0] = v.x; As[r][lk + 1] = v.y; As[r][lk + 2] = v.z; As[r][lk + 3] = v.w;
        }
        for (int i = tid; i < 32 * D_OUT; i += 256)
            ws[i] = wls[(size_t)s * D_H * D_OUT + kt * D_OUT + i];
        __syncthreads();
#pragma unroll
        for (int k = 0; k < 32; k++) {
            float a = As[crow][k];
#pragma unroll
            for (int j = 0; j < 5; j++)
                acc[j] = fmaf(a, ws[k * D_OUT + obase + j], acc[j]);
        }
        __syncthreads();
    }
#pragma unroll
    for (int j = 0; j < 5; j++)
        out[((size_t)s * BATCH + m0 + crow) * D_OUT + obase + j] = acc[j] + bls[s * D_OUT + obase + j];
}

// ---------------------------------------------------------------------------
// kernel_launch
// ---------------------------------------------------------------------------
extern "C" void kernel_launch(void* const* d_in, const int* in_sizes, int n_in,
                              void* d_out, int out_size) {
    const float* x   = (const float*)d_in[0];
    const float* wm0 = (const float*)d_in[1];
    const float* wv0 = (const float*)d_in[2];
    const float* bm0 = (const float*)d_in[3];
    const float* bv0 = (const float*)d_in[4];
    const float* wm1 = (const float*)d_in[5];
    const float* wv1 = (const float*)d_in[6];
    const float* bm1 = (const float*)d_in[7];
    const float* bv1 = (const float*)d_in[8];
    const float* wlm = (const float*)d_in[9];
    const float* wlv = (const float*)d_in[10];
    const float* blm = (const float*)d_in[11];
    const float* blv = (const float*)d_in[12];
    const float* we0 = (const float*)d_in[13];
    const float* be0 = (const float*)d_in[14];
    const float* we1 = (const float*)d_in[15];
    const float* be1 = (const float*)d_in[16];
    const float* wel = (const float*)d_in[17];
    const float* bel = (const float*)d_in[18];
    float* out = (float*)d_out;

    __nv_bfloat16 *xhi, *xlo, *w0hi, *w0lo, *w1hi, *w1lo, *a0hi, *a0lo;
    float *act1, *b0, *b1, *wl, *bl;
    cudaGetSymbolAddress((void**)&xhi,  g_xhi);
    cudaGetSymbolAddress((void**)&xlo,  g_xlo);
    cudaGetSymbolAddress((void**)&w0hi, g_w0hi);
    cudaGetSymbolAddress((void**)&w0lo, g_w0lo);
    cudaGetSymbolAddress((void**)&w1hi, g_w1hi);
    cudaGetSymbolAddress((void**)&w1lo, g_w1lo);
    cudaGetSymbolAddress((void**)&a0hi, g_a0hi);
    cudaGetSymbolAddress((void**)&a0lo, g_a0lo);
    cudaGetSymbolAddress((void**)&act1, g_act1);
    cudaGetSymbolAddress((void**)&b0,   g_b0);
    cudaGetSymbolAddress((void**)&b1,   g_b1);
    cudaGetSymbolAddress((void**)&wl,   g_wl);
    cudaGetSymbolAddress((void**)&bl,   g_bl);

    static bool attr_set = false;
    if (!attr_set) {
        cudaFuncSetAttribute(gemm_mma, cudaFuncAttributeMaxDynamicSharedMemorySize, SMEM_TOTAL);
        attr_set = true;
    }

    // prep: x split
    {
        int n = BATCH * K0PAD;
        prep_x<<<(n + 255) / 256, 256>>>(x, xhi, xlo);
    }
    // prep: sampled transposed weights (bf16 hi/lo)
    {
        dim3 blk(32, 8);
        dim3 g0(K0PAD / 32, D_H / 32, S_SAMP);
        prep_wt<<<g0, blk>>>(we0, wv0, wm0, w0hi, w0lo, D_IN, D_H, K0PAD);
        dim3 g1(D_H / 32, D_H / 32, S_SAMP);
        prep_wt<<<g1, blk>>>(we1, wv1, wm1, w1hi, w1lo, D_H, D_H, D_H);
    }
    // prep: biases + last layer
    {
        int total = S_SAMP * D_H;
        prep_sample<<<(total + 255) / 256, 256>>>(be0, bv0, bm0, b0, D_H, total);
        prep_sample<<<(total + 255) / 256, 256>>>(be1, bv1, bm1, b1, D_H, total);
        total = S_SAMP * D_H * D_OUT;
        prep_sample<<<(total + 255) / 256, 256>>>(wel, wlv, wlm, wl, D_H * D_OUT, total);
        total = S_SAMP * D_OUT;
        prep_sample<<<(total + 255) / 256, 256>>>(bel, blv, blm, bl, D_OUT, total);
    }

    // layer 0: act0 = relu(x @ W0 + b0) -> bf16 hi/lo
    {
        dim3 grid(D_H / GBN, BATCH / GBM, S_SAMP);
        gemm_mma<<<grid, 256, SMEM_TOTAL>>>(xhi, xlo, 0, K0PAD,
                                            w0hi, w0lo, b0,
                                            nullptr, a0hi, a0lo, 0);
    }
    // layer 1: act1 = relu(act0 @ W1 + b1) -> fp32
    {
        dim3 grid(D_H / GBN, BATCH / GBM, S_SAMP);
        gemm_mma<<<grid, 256, SMEM_TOTAL>>>(a0hi, a0lo, (size_t)BATCH * D_H, D_H,
                                            w1hi, w1lo, b1,
                                            act1, nullptr, nullptr, 1);
    }
    // final layer
    {
        dim3 grid(BATCH / 128, S_SAMP);
        layer_out<<<grid, 256>>>(act1, wl, bl, out);
    }
}